// round 1
// baseline (speedup 1.0000x reference)
#include <cuda_runtime.h>
#include <cstdint>

typedef unsigned long long ull;

#define IMG_W   512
#define OUT_W   507
#define STRIP   66      // output rows per block (divisible by 6)
#define NSTRIPS 8       // 8*66 = 528 >= 507

// ---------------- global accumulators (device-global scratch, no allocs) -----
__device__ double   g_acc;
__device__ unsigned g_minb, g_maxb;

static __device__ __forceinline__ unsigned encf(float f){
    unsigned u = __float_as_uint(f);
    return (u & 0x80000000u) ? ~u : (u | 0x80000000u);
}
static __device__ __forceinline__ float decf(unsigned u){
    unsigned b = (u & 0x80000000u) ? (u ^ 0x80000000u) : ~u;
    return __uint_as_float(b);
}

// ---------------- packed f32x2 helpers (sm_103a) ------------------------------
static __device__ __forceinline__ ull pk2(float a, float b){
    ull r; asm("mov.b64 %0, {%1, %2};" : "=l"(r) : "f"(a), "f"(b)); return r;
}
static __device__ __forceinline__ ull mul2(ull a, ull b){
    ull r; asm("mul.rn.f32x2 %0, %1, %2;" : "=l"(r) : "l"(a), "l"(b)); return r;
}
static __device__ __forceinline__ ull fma2(ull a, ull b, ull c){
    ull r; asm("fma.rn.f32x2 %0, %1, %2, %3;" : "=l"(r) : "l"(a), "l"(b), "l"(c)); return r;
}
static __device__ __forceinline__ float lo2(ull a){ return __uint_as_float((unsigned)a); }
static __device__ __forceinline__ float hi2(ull a){ return __uint_as_float((unsigned)(a >> 32)); }

// ---------------- gaussian weights (w_size=6, sigma=1.5, normalized) ---------
#define GW0 0.03802585f
#define GW1 0.11551231f
#define GW2 0.22498725f
#define GW3 0.28097506f
// taps: [GW0, GW1, GW2, GW3, GW2, GW1]

// horizontal 6-tap, weights as immediates -> FFMA-imm (rt=1)
#define HTAP(m0,m1,m2,m3,m4,m5) \
    fmaf((m5), GW1, fmaf((m4), GW2, fmaf((m3), GW3, fmaf((m2), GW2, fmaf((m1), GW1, (m0) * GW0)))))

static __device__ __forceinline__ float ssim_val(float mu1, float mu2, float S, float exy,
                                                 float C1, float C2){
    float mu12 = mu1 * mu2;
    float msum = fmaf(mu1, mu1, mu2 * mu2);
    float v1   = fmaf(2.0f, exy, C2) - 2.0f * mu12;   // 2*sigma12 + C2
    float v2   = (S + C2) - msum;                      // sigma1^2 + sigma2^2 + C2
    float num  = fmaf(2.0f, mu12, C1) * v1;
    float den  = (msum + C1) * v2;
    return __fdividef(num, den);
}

// ---------------- kernels -----------------------------------------------------
__global__ void k_init(){
    g_acc  = 0.0;
    g_minb = 0xFFFFFFFFu;   // encf(+inf) upper bound
    g_maxb = 0u;            // encf(-inf) lower bound
}

__global__ void k_minmax(const float4* __restrict__ x, int n4){
    float mn = 3.4028235e38f, mx = -3.4028235e38f;
    int stride = gridDim.x * blockDim.x;
    for (int i = blockIdx.x * blockDim.x + threadIdx.x; i < n4; i += stride){
        float4 v = x[i];
        mn = fminf(mn, fminf(fminf(v.x, v.y), fminf(v.z, v.w)));
        mx = fmaxf(mx, fmaxf(fmaxf(v.x, v.y), fmaxf(v.z, v.w)));
    }
    #pragma unroll
    for (int o = 16; o > 0; o >>= 1){
        mn = fminf(mn, __shfl_xor_sync(0xFFFFFFFFu, mn, o));
        mx = fmaxf(mx, __shfl_xor_sync(0xFFFFFFFFu, mx, o));
    }
    __shared__ float smn[8], smx[8];
    int wid = threadIdx.x >> 5, lane = threadIdx.x & 31;
    if (lane == 0){ smn[wid] = mn; smx[wid] = mx; }
    __syncthreads();
    if (threadIdx.x == 0){
        mn = smn[0]; mx = smx[0];
        #pragma unroll
        for (int w = 1; w < 8; ++w){ mn = fminf(mn, smn[w]); mx = fmaxf(mx, smx[w]); }
        atomicMin(&g_minb, encf(mn));
        atomicMax(&g_maxb, encf(mx));
    }
}

__global__ void __launch_bounds__(256, 2)
k_ssim(const float* __restrict__ X, const float* __restrict__ Y){
    __shared__ float sx[2][520];
    __shared__ float sy[2][520];
    __shared__ float sred[8];

    const int tid  = threadIdx.x;
    const int c0   = tid * 2;
    const int base = blockIdx.x * STRIP;
    const size_t ioff = (size_t)blockIdx.y * (size_t)(IMG_W * IMG_W);
    const float* xi = X + ioff;
    const float* yi = Y + ioff;

    // dynamic range (written by k_minmax, previous launch in same stream)
    const float maxv = decf(g_maxb);
    const float minv = decf(g_minb);
    const float Ldyn = (maxv > 128.0f ? 255.0f : 1.0f) - (minv < -0.5f ? -1.0f : 0.0f);
    const float C1 = (0.01f * Ldyn) * (0.01f * Ldyn);
    const float C2 = (0.03f * Ldyn) * (0.03f * Ldyn);

    // zero the smem pad region (cols 512..519)
    if (tid < 8){
        sx[0][512 + tid] = 0.0f; sx[1][512 + tid] = 0.0f;
        sy[0][512 + tid] = 0.0f; sy[1][512 + tid] = 0.0f;
    }

    // prologue: load input row "base" into buffer 0
    {
        float2 vx = *(const float2*)(xi + (size_t)base * IMG_W + c0);
        float2 vy = *(const float2*)(yi + (size_t)base * IMG_W + c0);
        *(float2*)(&sx[0][c0]) = vx;
        *(float2*)(&sy[0][c0]) = vy;
    }
    __syncthreads();

    // ring of horizontal sums: 6 rows x {hx0,hx1,hy0,hy1,hp0,hp1,hq0,hq1}
    float ring[6][8];
    float acc = 0.0f;

    #pragma unroll 1
    for (int i6 = 0; i6 < 72; i6 += 6){
        #pragma unroll
        for (int p = 0; p < 6; ++p){
            const int i = i6 + p;
            if (i < 71){
                const int cur = i & 1;
                const int nxt = cur ^ 1;

                // issue prefetch of next input row early (consumed after compute)
                const int rnext = base + i + 1;
                const bool doload = (i + 1 < 71) && (rnext < IMG_W);
                float2 nx, ny;
                if (doload){
                    nx = *(const float2*)(xi + (size_t)rnext * IMG_W + c0);
                    ny = *(const float2*)(yi + (size_t)rnext * IMG_W + c0);
                }

                // ---- horizontal pass on current row (cols c0..c0+7) ----
                const float* bx = &sx[cur][c0];
                const float* by = &sy[cur][c0];
                float2 X0 = *(const float2*)(bx + 0);
                float2 X1 = *(const float2*)(bx + 2);
                float2 X2 = *(const float2*)(bx + 4);
                float2 X3 = *(const float2*)(bx + 6);
                float2 Y0 = *(const float2*)(by + 0);
                float2 Y1 = *(const float2*)(by + 2);
                float2 Y2 = *(const float2*)(by + 4);
                float2 Y3 = *(const float2*)(by + 6);

                ull xp0 = pk2(X0.x, X0.y), xp1 = pk2(X1.x, X1.y);
                ull xp2 = pk2(X2.x, X2.y), xp3 = pk2(X3.x, X3.y);
                ull yp0 = pk2(Y0.x, Y0.y), yp1 = pk2(Y1.x, Y1.y);
                ull yp2 = pk2(Y2.x, Y2.y), yp3 = pk2(Y3.x, Y3.y);

                // p = x^2 + y^2 ; q = x*y  (packed, 2 cols per op)
                ull pp0 = fma2(yp0, yp0, mul2(xp0, xp0));
                ull pp1 = fma2(yp1, yp1, mul2(xp1, xp1));
                ull pp2 = fma2(yp2, yp2, mul2(xp2, xp2));
                ull pp3 = fma2(yp3, yp3, mul2(xp3, xp3));
                ull qq0 = mul2(xp0, yp0), qq1 = mul2(xp1, yp1);
                ull qq2 = mul2(xp2, yp2), qq3 = mul2(xp3, yp3);

                float p0 = lo2(pp0), p1 = hi2(pp0), p2 = lo2(pp1), p3 = hi2(pp1);
                float p4 = lo2(pp2), p5 = hi2(pp2), p6 = lo2(pp3);
                float q0 = lo2(qq0), q1 = hi2(qq0), q2 = lo2(qq1), q3 = hi2(qq1);
                float q4 = lo2(qq2), q5 = hi2(qq2), q6 = lo2(qq3);

                ring[p][0] = HTAP(X0.x, X0.y, X1.x, X1.y, X2.x, X2.y);
                ring[p][1] = HTAP(X0.y, X1.x, X1.y, X2.x, X2.y, X3.x);
                ring[p][2] = HTAP(Y0.x, Y0.y, Y1.x, Y1.y, Y2.x, Y2.y);
                ring[p][3] = HTAP(Y0.y, Y1.x, Y1.y, Y2.x, Y2.y, Y3.x);
                ring[p][4] = HTAP(p0, p1, p2, p3, p4, p5);
                ring[p][5] = HTAP(p1, p2, p3, p4, p5, p6);
                ring[p][6] = HTAP(q0, q1, q2, q3, q4, q5);
                ring[p][7] = HTAP(q1, q2, q3, q4, q5, q6);

                // ---- vertical pass + SSIM (output row i-5) ----
                if (i >= 5){
                    const int oy = base + i - 5;
                    if (oy < OUT_W && c0 < OUT_W){
                        float v[8];
                        #pragma unroll
                        for (int j = 0; j < 8; ++j){
                            float s = ring[(p + 1) % 6][j] * GW0;
                            s = fmaf(ring[(p + 2) % 6][j], GW1, s);
                            s = fmaf(ring[(p + 3) % 6][j], GW2, s);
                            s = fmaf(ring[(p + 4) % 6][j], GW3, s);
                            s = fmaf(ring[(p + 5) % 6][j], GW2, s);
                            s = fmaf(ring[p][j],           GW1, s);
                            v[j] = s;
                        }
                        acc += ssim_val(v[0], v[2], v[4], v[6], C1, C2);
                        if (c0 + 1 < OUT_W)
                            acc += ssim_val(v[1], v[3], v[5], v[7], C1, C2);
                    }
                }

                // commit prefetched row to the other buffer
                if (doload){
                    *(float2*)(&sx[nxt][c0]) = nx;
                    *(float2*)(&sy[nxt][c0]) = ny;
                }
                __syncthreads();
            }
        }
    }

    // ---- block reduction ----
    #pragma unroll
    for (int o = 16; o > 0; o >>= 1)
        acc += __shfl_xor_sync(0xFFFFFFFFu, acc, o);
    const int wid = tid >> 5, lane = tid & 31;
    if (lane == 0) sred[wid] = acc;
    __syncthreads();
    if (tid == 0){
        float s = sred[0];
        #pragma unroll
        for (int w = 1; w < 8; ++w) s += sred[w];
        atomicAdd(&g_acc, (double)s);
    }
}

__global__ void k_fin(float* out, double inv_n){
    out[0] = (float)((1.0 - g_acc * inv_n) * 0.5);
}

// ---------------- launch --------------------------------------------------------
extern "C" void kernel_launch(void* const* d_in, const int* in_sizes, int n_in,
                              void* d_out, int out_size){
    const float* X = (const float*)d_in[0];  // output  (y_pred)
    const float* Y = (const float*)d_in[1];  // target  (y_true)

    const int nelem = in_sizes[0];
    const int nimg  = nelem / (IMG_W * IMG_W);          // B*C maps
    const double n_out = (double)nimg * (double)OUT_W * (double)OUT_W;

    k_init<<<1, 1>>>();
    k_minmax<<<1184, 256>>>((const float4*)X, nelem / 4);
    dim3 grid(NSTRIPS, nimg);
    k_ssim<<<grid, 256>>>(X, Y);
    k_fin<<<1, 1>>>((float*)d_out, 1.0 / n_out);
}

// round 2
// speedup vs baseline: 1.2481x; 1.2481x over previous
#include <cuda_runtime.h>
#include <cstdint>

typedef unsigned long long ull;

#define IMG_W   512
#define OUT_W   507
#define STRIP   66      // output rows per block
#define NSTRIPS 8       // 8*66 = 528 >= 507
#define NB_MM   1184

// ---------------- device-global scratch (no allocs) --------------------------
__device__ float g_mn[NB_MM], g_mx[NB_MM];
__device__ float g_part[1024];          // NSTRIPS * nimg <= 768

// ---------------- packed f32x2 helpers (sm_103a) ------------------------------
static __device__ __forceinline__ ull pk2(float a, float b){
    ull r; asm("mov.b64 %0, {%1, %2};" : "=l"(r) : "f"(a), "f"(b)); return r;
}
static __device__ __forceinline__ ull mul2(ull a, ull b){
    ull r; asm("mul.rn.f32x2 %0, %1, %2;" : "=l"(r) : "l"(a), "l"(b)); return r;
}
static __device__ __forceinline__ ull add2(ull a, ull b){
    ull r; asm("add.rn.f32x2 %0, %1, %2;" : "=l"(r) : "l"(a), "l"(b)); return r;
}
static __device__ __forceinline__ ull fma2(ull a, ull b, ull c){
    ull r; asm("fma.rn.f32x2 %0, %1, %2, %3;" : "=l"(r) : "l"(a), "l"(b), "l"(c)); return r;
}
static __device__ __forceinline__ float lo2(ull a){ return __uint_as_float((unsigned)a); }
static __device__ __forceinline__ float hi2(ull a){ return __uint_as_float((unsigned)(a >> 32)); }

// ---------------- gaussian weights (w_size=6, sigma=1.5, normalized) ---------
#define GW0 0.03802585f
#define GW1 0.11551231f
#define GW2 0.22498725f
#define GW3 0.28097506f

// ---------------- min/max partials kernel -------------------------------------
__global__ void k_minmax(const float4* __restrict__ x, int n4){
    float mn = 3.4028235e38f, mx = -3.4028235e38f;
    int stride = gridDim.x * blockDim.x;
    for (int i = blockIdx.x * blockDim.x + threadIdx.x; i < n4; i += stride){
        float4 v = x[i];
        mn = fminf(mn, fminf(fminf(v.x, v.y), fminf(v.z, v.w)));
        mx = fmaxf(mx, fmaxf(fmaxf(v.x, v.y), fmaxf(v.z, v.w)));
    }
    #pragma unroll
    for (int o = 16; o > 0; o >>= 1){
        mn = fminf(mn, __shfl_xor_sync(0xFFFFFFFFu, mn, o));
        mx = fmaxf(mx, __shfl_xor_sync(0xFFFFFFFFu, mx, o));
    }
    __shared__ float smn[8], smx[8];
    int wid = threadIdx.x >> 5, lane = threadIdx.x & 31;
    if (lane == 0){ smn[wid] = mn; smx[wid] = mx; }
    __syncthreads();
    if (threadIdx.x == 0){
        mn = smn[0]; mx = smx[0];
        #pragma unroll
        for (int w = 1; w < 8; ++w){ mn = fminf(mn, smn[w]); mx = fmaxf(mx, smx[w]); }
        g_mn[blockIdx.x] = mn;
        g_mx[blockIdx.x] = mx;
    }
}

// 6-tap packed horizontal/vertical MAC: taps [GW0,GW1,GW2,GW3,GW2,GW1]
#define HMAC(d, v0, v1, v2, v3, v4, v5) \
    d = mul2((v0), W0); d = fma2((v1), W1, d); d = fma2((v2), W2, d); \
    d = fma2((v3), W3, d); d = fma2((v4), W2, d); d = fma2((v5), W1, d)

// One input row: horizontal pass into ring[P], then (if output row valid)
// vertical pass + SSIM for output row I-5. P must be a compile-time literal.
#define ROW_STEP(P, I) do { \
    const int slot_ = (I) & 3; \
    const float* bx_ = &sx[slot_][c0]; \
    const float* by_ = &sy[slot_][c0]; \
    float2 X0_ = *(const float2*)(bx_ + 0); \
    float2 X1_ = *(const float2*)(bx_ + 2); \
    float2 X2_ = *(const float2*)(bx_ + 4); \
    float2 X3_ = *(const float2*)(bx_ + 6); \
    float2 Y0_ = *(const float2*)(by_ + 0); \
    float2 Y1_ = *(const float2*)(by_ + 2); \
    float2 Y2_ = *(const float2*)(by_ + 4); \
    float2 Y3_ = *(const float2*)(by_ + 6); \
    ull xp0_ = pk2(X0_.x, X0_.y), xp1_ = pk2(X1_.x, X1_.y); \
    ull xp2_ = pk2(X2_.x, X2_.y), xp3_ = pk2(X3_.x, X3_.y); \
    ull yp0_ = pk2(Y0_.x, Y0_.y), yp1_ = pk2(Y1_.x, Y1_.y); \
    ull yp2_ = pk2(Y2_.x, Y2_.y), yp3_ = pk2(Y3_.x, Y3_.y); \
    ull pp0_ = fma2(yp0_, yp0_, mul2(xp0_, xp0_)); \
    ull pp1_ = fma2(yp1_, yp1_, mul2(xp1_, xp1_)); \
    ull pp2_ = fma2(yp2_, yp2_, mul2(xp2_, xp2_)); \
    ull pp3_ = fma2(yp3_, yp3_, mul2(xp3_, xp3_)); \
    ull qq0_ = mul2(xp0_, yp0_), qq1_ = mul2(xp1_, yp1_); \
    ull qq2_ = mul2(xp2_, yp2_), qq3_ = mul2(xp3_, yp3_); \
    { ull d_; HMAC(d_, xp0_, pk2(X0_.y, X1_.x), xp1_, pk2(X1_.y, X2_.x), xp2_, pk2(X2_.y, X3_.x)); ring[(P)][0] = d_; } \
    { ull d_; HMAC(d_, yp0_, pk2(Y0_.y, Y1_.x), yp1_, pk2(Y1_.y, Y2_.x), yp2_, pk2(Y2_.y, Y3_.x)); ring[(P)][1] = d_; } \
    { ull d_; HMAC(d_, pp0_, pk2(hi2(pp0_), lo2(pp1_)), pp1_, pk2(hi2(pp1_), lo2(pp2_)), pp2_, pk2(hi2(pp2_), lo2(pp3_))); ring[(P)][2] = d_; } \
    { ull d_; HMAC(d_, qq0_, pk2(hi2(qq0_), lo2(qq1_)), qq1_, pk2(hi2(qq1_), lo2(qq2_)), qq2_, pk2(hi2(qq2_), lo2(qq3_))); ring[(P)][3] = d_; } \
    if ((I) >= 5 && (I) < 71 && (base + (I) - 5) < OUT_W){ \
        ull v0_, v1_, v2_, v3_; \
        HMAC(v0_, ring[((P)+1)%6][0], ring[((P)+2)%6][0], ring[((P)+3)%6][0], ring[((P)+4)%6][0], ring[((P)+5)%6][0], ring[(P)][0]); \
        HMAC(v1_, ring[((P)+1)%6][1], ring[((P)+2)%6][1], ring[((P)+3)%6][1], ring[((P)+4)%6][1], ring[((P)+5)%6][1], ring[(P)][1]); \
        HMAC(v2_, ring[((P)+1)%6][2], ring[((P)+2)%6][2], ring[((P)+3)%6][2], ring[((P)+4)%6][2], ring[((P)+5)%6][2], ring[(P)][2]); \
        HMAC(v3_, ring[((P)+1)%6][3], ring[((P)+2)%6][3], ring[((P)+3)%6][3], ring[((P)+4)%6][3], ring[((P)+5)%6][3], ring[(P)][3]); \
        ull mu12_ = mul2(v0_, v1_); \
        ull msum_ = fma2(v1_, v1_, mul2(v0_, v0_)); \
        ull t1_ = fma2(mu12_, NTWO, fma2(v3_, TWO, C2p)); \
        ull t2_ = fma2(msum_, NONE, add2(v2_, C2p)); \
        ull num_ = mul2(fma2(mu12_, TWO, C1p), t1_); \
        ull den_ = mul2(add2(msum_, C1p), t2_); \
        float nl_ = lo2(num_), nh_ = hi2(num_); \
        float dl_ = lo2(den_), dh_ = hi2(den_); \
        if (hi_ok)      acc += __fdividef(fmaf(nl_, dh_, nh_ * dl_), dl_ * dh_); \
        else if (lo_ok) acc += __fdividef(nl_, dl_); \
    } \
} while(0)

// Process rows ia, ia+1 with one barrier; prefetch rows ia+2, ia+3 during compute.
// KP2 must be a literal in {0, 2, 4}.
#define PAIR_STEP(KP2, I6) do { \
    const int ia_ = (I6) + (KP2); \
    const int ra_ = base + ia_ + 2; \
    const int rb_ = base + ia_ + 3; \
    const bool la_ = (ia_ + 2 < 72) && (ra_ < IMG_W); \
    const bool lb_ = (ia_ + 3 < 72) && (rb_ < IMG_W); \
    float2 ax_, ay_, bxx_, byy_; \
    if (la_){ ax_  = *(const float2*)(xi + (size_t)ra_ * IMG_W + c0); \
              ay_  = *(const float2*)(yi + (size_t)ra_ * IMG_W + c0); } \
    if (lb_){ bxx_ = *(const float2*)(xi + (size_t)rb_ * IMG_W + c0); \
              byy_ = *(const float2*)(yi + (size_t)rb_ * IMG_W + c0); } \
    ROW_STEP(KP2, ia_); \
    ROW_STEP((KP2)+1, ia_ + 1); \
    if (la_){ int s_ = (ia_ + 2) & 3; *(float2*)&sx[s_][c0] = ax_;  *(float2*)&sy[s_][c0] = ay_;  } \
    if (lb_){ int s_ = (ia_ + 3) & 3; *(float2*)&sx[s_][c0] = bxx_; *(float2*)&sy[s_][c0] = byy_; } \
    __syncthreads(); \
} while(0)

__global__ void __launch_bounds__(256)
k_ssim(const float* __restrict__ X, const float* __restrict__ Y, int strip0){
    __shared__ float sx[4][520];
    __shared__ float sy[4][520];
    __shared__ float smn[8], smx[8];
    __shared__ float sC[2];

    const int tid  = threadIdx.x;
    const int c0   = tid * 2;
    const int base = (strip0 + blockIdx.x) * STRIP;
    const size_t ioff = (size_t)blockIdx.y * (size_t)(IMG_W * IMG_W);
    const float* xi = X + ioff;
    const float* yi = Y + ioff;
    const bool lo_ok = (c0     < OUT_W);
    const bool hi_ok = (c0 + 1 < OUT_W);

    // ---- reduce min/max partials -> C1, C2 ----
    {
        float mn = 3.4028235e38f, mx = -3.4028235e38f;
        for (int i = tid; i < NB_MM; i += 256){
            mn = fminf(mn, g_mn[i]);
            mx = fmaxf(mx, g_mx[i]);
        }
        #pragma unroll
        for (int o = 16; o > 0; o >>= 1){
            mn = fminf(mn, __shfl_xor_sync(0xFFFFFFFFu, mn, o));
            mx = fmaxf(mx, __shfl_xor_sync(0xFFFFFFFFu, mx, o));
        }
        int wid = tid >> 5, lane = tid & 31;
        if (lane == 0){ smn[wid] = mn; smx[wid] = mx; }
    }

    // zero smem pads (cols 512..519 in all 4 slots)
    if (tid < 8){
        #pragma unroll
        for (int s = 0; s < 4; ++s){ sx[s][512 + tid] = 0.0f; sy[s][512 + tid] = 0.0f; }
    }

    // preload rows base+0, base+1 into slots 0,1
    #pragma unroll
    for (int r0 = 0; r0 < 2; ++r0){
        int r = base + r0;
        if (r < IMG_W){
            *(float2*)&sx[r0][c0] = *(const float2*)(xi + (size_t)r * IMG_W + c0);
            *(float2*)&sy[r0][c0] = *(const float2*)(yi + (size_t)r * IMG_W + c0);
        }
    }
    __syncthreads();

    if (tid == 0){
        float mn = smn[0], mx = smx[0];
        #pragma unroll
        for (int w = 1; w < 8; ++w){ mn = fminf(mn, smn[w]); mx = fmaxf(mx, smx[w]); }
        float Ldyn = (mx > 128.0f ? 255.0f : 1.0f) - (mn < -0.5f ? -1.0f : 0.0f);
        sC[0] = (0.01f * Ldyn) * (0.01f * Ldyn);
        sC[1] = (0.03f * Ldyn) * (0.03f * Ldyn);
    }
    __syncthreads();

    const float C1 = sC[0], C2 = sC[1];
    const ull W0  = pk2(GW0, GW0), W1 = pk2(GW1, GW1);
    const ull W2  = pk2(GW2, GW2), W3 = pk2(GW3, GW3);
    const ull C1p = pk2(C1, C1),   C2p = pk2(C2, C2);
    const ull TWO = pk2(2.0f, 2.0f), NTWO = pk2(-2.0f, -2.0f), NONE = pk2(-1.0f, -1.0f);

    ull ring[6][4];
    float acc = 0.0f;

    #pragma unroll 1
    for (int i6 = 0; i6 < 72; i6 += 6){
        PAIR_STEP(0, i6);
        PAIR_STEP(2, i6);
        PAIR_STEP(4, i6);
    }

    // ---- block reduction -> per-block partial ----
    #pragma unroll
    for (int o = 16; o > 0; o >>= 1)
        acc += __shfl_xor_sync(0xFFFFFFFFu, acc, o);
    const int wid = tid >> 5, lane = tid & 31;
    if (lane == 0) smn[wid] = acc;   // reuse smn
    __syncthreads();
    if (tid == 0){
        float s = smn[0];
        #pragma unroll
        for (int w = 1; w < 8; ++w) s += smn[w];
        g_part[blockIdx.y * NSTRIPS + (strip0 + blockIdx.x)] = s;
    }
}

__global__ void k_fin(float* out, int n, double inv_n){
    double s = 0.0;
    for (int i = threadIdx.x; i < n; i += 256) s += (double)g_part[i];
    #pragma unroll
    for (int o = 16; o > 0; o >>= 1)
        s += __shfl_xor_sync(0xFFFFFFFFu, s, o);
    __shared__ double sd[8];
    int wid = threadIdx.x >> 5, lane = threadIdx.x & 31;
    if (lane == 0) sd[wid] = s;
    __syncthreads();
    if (threadIdx.x == 0){
        double t = 0.0;
        #pragma unroll
        for (int w = 0; w < 8; ++w) t += sd[w];
        out[0] = (float)((1.0 - t * inv_n) * 0.5);
    }
}

// ---------------- launch --------------------------------------------------------
extern "C" void kernel_launch(void* const* d_in, const int* in_sizes, int n_in,
                              void* d_out, int out_size){
    const float* X = (const float*)d_in[0];  // y_pred
    const float* Y = (const float*)d_in[1];  // y_true

    const int nelem = in_sizes[0];
    const int nimg  = nelem / (IMG_W * IMG_W);
    const double n_out = (double)nimg * (double)OUT_W * (double)OUT_W;

    k_minmax<<<NB_MM, 256>>>((const float4*)X, nelem / 4);
    dim3 grid(NSTRIPS / 2, nimg);
    k_ssim<<<grid, 256>>>(X, Y, 0);
    k_ssim<<<grid, 256>>>(X, Y, NSTRIPS / 2);
    k_fin<<<1, 256>>>((float*)d_out, nimg * NSTRIPS, 1.0 / n_out);
}

// round 3
// speedup vs baseline: 1.4864x; 1.1910x over previous
#include <cuda_runtime.h>
#include <cstdint>

typedef unsigned long long ull;

#define IMG_W 512
#define OUT_W 507
#define NSTR  6      // strips per image
#define STRIP 85     // output rows per strip (6*85=510 >= 507)
#define NROWS 90     // input rows per strip (STRIP + 5 halo)
#define NB_MM 1184

// ---------------- device-global scratch (no allocs) --------------------------
__device__ float    g_mn[NB_MM], g_mx[NB_MM];
__device__ float    g_part[1024];
__device__ unsigned g_done;          // zero-init; last block resets to 0 each run

// ---------------- packed f32x2 helpers (sm_103a) ------------------------------
static __device__ __forceinline__ ull pk2(float a, float b){
    ull r; asm("mov.b64 %0, {%1, %2};" : "=l"(r) : "f"(a), "f"(b)); return r;
}
static __device__ __forceinline__ ull mul2(ull a, ull b){
    ull r; asm("mul.rn.f32x2 %0, %1, %2;" : "=l"(r) : "l"(a), "l"(b)); return r;
}
static __device__ __forceinline__ ull add2(ull a, ull b){
    ull r; asm("add.rn.f32x2 %0, %1, %2;" : "=l"(r) : "l"(a), "l"(b)); return r;
}
static __device__ __forceinline__ ull fma2(ull a, ull b, ull c){
    ull r; asm("fma.rn.f32x2 %0, %1, %2, %3;" : "=l"(r) : "l"(a), "l"(b), "l"(c)); return r;
}
static __device__ __forceinline__ float lo2(ull a){ return __uint_as_float((unsigned)a); }
static __device__ __forceinline__ float hi2(ull a){ return __uint_as_float((unsigned)(a >> 32)); }
static __device__ __forceinline__ void pref2(const float* p){
    asm volatile("prefetch.global.L2 [%0];" :: "l"(p));
}

// ---------------- gaussian weights (w_size=6, sigma=1.5, normalized) ---------
#define GW0 0.03802585f
#define GW1 0.11551231f
#define GW2 0.22498725f
#define GW3 0.28097506f

// ---------------- min/max partials kernel -------------------------------------
__global__ void k_minmax(const float4* __restrict__ x, int n4){
    float mn = 3.4028235e38f, mx = -3.4028235e38f;
    int stride = gridDim.x * blockDim.x;
    for (int i = blockIdx.x * blockDim.x + threadIdx.x; i < n4; i += stride){
        float4 v = x[i];
        mn = fminf(mn, fminf(fminf(v.x, v.y), fminf(v.z, v.w)));
        mx = fmaxf(mx, fmaxf(fmaxf(v.x, v.y), fmaxf(v.z, v.w)));
    }
    #pragma unroll
    for (int o = 16; o > 0; o >>= 1){
        mn = fminf(mn, __shfl_xor_sync(0xFFFFFFFFu, mn, o));
        mx = fmaxf(mx, __shfl_xor_sync(0xFFFFFFFFu, mx, o));
    }
    __shared__ float smn[8], smx[8];
    int wid = threadIdx.x >> 5, lane = threadIdx.x & 31;
    if (lane == 0){ smn[wid] = mn; smx[wid] = mx; }
    __syncthreads();
    if (threadIdx.x == 0){
        mn = smn[0]; mx = smx[0];
        #pragma unroll
        for (int w = 1; w < 8; ++w){ mn = fminf(mn, smn[w]); mx = fmaxf(mx, smx[w]); }
        g_mn[blockIdx.x] = mn;
        g_mx[blockIdx.x] = mx;
    }
}

// 6-tap packed MAC: taps [GW0,GW1,GW2,GW3,GW2,GW1]
#define HMAC(d, v0, v1, v2, v3, v4, v5) \
    d = mul2((v0), W0); d = fma2((v1), W1, d); d = fma2((v2), W2, d); \
    d = fma2((v3), W3, d); d = fma2((v4), W2, d); d = fma2((v5), W1, d)

// load one input row (both tensors) into register set S (S literal)
#define LOADROW(S, R) do { \
    const float* xr_ = xi + (size_t)(R) * IMG_W; \
    const float* yr_ = yi + (size_t)(R) * IMG_W; \
    rx[S][0] = *(const float2*)(xr_ + o0); rx[S][1] = *(const float2*)(xr_ + o1); \
    rx[S][2] = *(const float2*)(xr_ + o2); rx[S][3] = *(const float2*)(xr_ + o3); \
    ry[S][0] = *(const float2*)(yr_ + o0); ry[S][1] = *(const float2*)(yr_ + o1); \
    ry[S][2] = *(const float2*)(yr_ + o2); ry[S][3] = *(const float2*)(yr_ + o3); \
} while(0)

// One row-step. P literal 0..5. Computes row i=I6+P from set P%3, LDG-prefetches
// row i+2 into set (P+2)%3, L2-prefetches row i+6, emits output row i-5.
#define ROW_STEP(P, I6) do { \
    const int i_ = (I6) + (P); \
    { const int rp_ = base + i_ + 6; \
      if (i_ + 6 < NROWS && rp_ < IMG_W){ \
          pref2(xi + (size_t)rp_ * IMG_W + c0); \
          pref2(yi + (size_t)rp_ * IMG_W + c0); } } \
    { const int rl_ = base + i_ + 2; \
      if (i_ + 2 < NROWS && rl_ < IMG_W){ LOADROW(((P)+2)%3, rl_); } } \
    { \
        float2 X0_ = rx[(P)%3][0], X1_ = rx[(P)%3][1], X2_ = rx[(P)%3][2], X3_ = rx[(P)%3][3]; \
        float2 Y0_ = ry[(P)%3][0], Y1_ = ry[(P)%3][1], Y2_ = ry[(P)%3][2], Y3_ = ry[(P)%3][3]; \
        ull xp0_ = pk2(X0_.x, X0_.y), xp1_ = pk2(X1_.x, X1_.y); \
        ull xp2_ = pk2(X2_.x, X2_.y), xp3_ = pk2(X3_.x, X3_.y); \
        ull yp0_ = pk2(Y0_.x, Y0_.y), yp1_ = pk2(Y1_.x, Y1_.y); \
        ull yp2_ = pk2(Y2_.x, Y2_.y), yp3_ = pk2(Y3_.x, Y3_.y); \
        ull pp0_ = fma2(yp0_, yp0_, mul2(xp0_, xp0_)); \
        ull pp1_ = fma2(yp1_, yp1_, mul2(xp1_, xp1_)); \
        ull pp2_ = fma2(yp2_, yp2_, mul2(xp2_, xp2_)); \
        ull pp3_ = fma2(yp3_, yp3_, mul2(xp3_, xp3_)); \
        ull qq0_ = mul2(xp0_, yp0_), qq1_ = mul2(xp1_, yp1_); \
        ull qq2_ = mul2(xp2_, yp2_), qq3_ = mul2(xp3_, yp3_); \
        { ull d_; HMAC(d_, xp0_, pk2(X0_.y, X1_.x), xp1_, pk2(X1_.y, X2_.x), xp2_, pk2(X2_.y, X3_.x)); ring[(P)][0] = d_; } \
        { ull d_; HMAC(d_, yp0_, pk2(Y0_.y, Y1_.x), yp1_, pk2(Y1_.y, Y2_.x), yp2_, pk2(Y2_.y, Y3_.x)); ring[(P)][1] = d_; } \
        { ull d_; HMAC(d_, pp0_, pk2(hi2(pp0_), lo2(pp1_)), pp1_, pk2(hi2(pp1_), lo2(pp2_)), pp2_, pk2(hi2(pp2_), lo2(pp3_))); ring[(P)][2] = d_; } \
        { ull d_; HMAC(d_, qq0_, pk2(hi2(qq0_), lo2(qq1_)), qq1_, pk2(hi2(qq1_), lo2(qq2_)), qq2_, pk2(hi2(qq2_), lo2(qq3_))); ring[(P)][3] = d_; } \
    } \
    if (i_ >= 5 && (base + i_ - 5) < OUT_W){ \
        ull v0_, v1_, v2_, v3_; \
        HMAC(v0_, ring[((P)+1)%6][0], ring[((P)+2)%6][0], ring[((P)+3)%6][0], ring[((P)+4)%6][0], ring[((P)+5)%6][0], ring[(P)][0]); \
        HMAC(v1_, ring[((P)+1)%6][1], ring[((P)+2)%6][1], ring[((P)+3)%6][1], ring[((P)+4)%6][1], ring[((P)+5)%6][1], ring[(P)][1]); \
        HMAC(v2_, ring[((P)+1)%6][2], ring[((P)+2)%6][2], ring[((P)+3)%6][2], ring[((P)+4)%6][2], ring[((P)+5)%6][2], ring[(P)][2]); \
        HMAC(v3_, ring[((P)+1)%6][3], ring[((P)+2)%6][3], ring[((P)+3)%6][3], ring[((P)+4)%6][3], ring[((P)+5)%6][3], ring[(P)][3]); \
        ull mu12_ = mul2(v0_, v1_); \
        ull msum_ = fma2(v1_, v1_, mul2(v0_, v0_)); \
        ull t1_ = fma2(mu12_, NTWO, fma2(v3_, TWO, C2p)); \
        ull t2_ = fma2(msum_, NONE, add2(v2_, C2p)); \
        ull num_ = mul2(fma2(mu12_, TWO, C1p), t1_); \
        ull den_ = mul2(add2(msum_, C1p), t2_); \
        float nl_ = lo2(num_), nh_ = hi2(num_); \
        float dl_ = lo2(den_), dh_ = hi2(den_); \
        if (hi_ok)      acc += __fdividef(fmaf(nl_, dh_, nh_ * dl_), dl_ * dh_); \
        else if (lo_ok) acc += __fdividef(nl_, dl_); \
    } \
} while(0)

__global__ void __launch_bounds__(256)
k_ssim(const float* __restrict__ X, const float* __restrict__ Y,
       float* __restrict__ out, int nblk, double inv_n){
    __shared__ float    smn[8], smx[8], sC[2];
    __shared__ double   sd[8];
    __shared__ unsigned s_tick;

    const int tid   = threadIdx.x;
    const int c0    = tid * 2;
    const int bx    = blockIdx.x;
    const int strip = bx % NSTR;
    const int img   = bx / NSTR;
    const int base  = strip * STRIP;
    const float* xi = X + (size_t)img * (IMG_W * IMG_W);
    const float* yi = Y + (size_t)img * (IMG_W * IMG_W);
    const bool lo_ok = (c0     < OUT_W);
    const bool hi_ok = (c0 + 1 < OUT_W);

    // clamped column offsets (edge threads read in-bounds garbage; outputs masked)
    const int o0 = c0;
    const int o1 = min(c0 + 2, 510);
    const int o2 = min(c0 + 4, 510);
    const int o3 = min(c0 + 6, 510);

    // ---- reduce min/max partials -> C1, C2 ----
    {
        float mn = 3.4028235e38f, mx = -3.4028235e38f;
        for (int i = tid; i < NB_MM; i += 256){
            mn = fminf(mn, g_mn[i]);
            mx = fmaxf(mx, g_mx[i]);
        }
        #pragma unroll
        for (int o = 16; o > 0; o >>= 1){
            mn = fminf(mn, __shfl_xor_sync(0xFFFFFFFFu, mn, o));
            mx = fmaxf(mx, __shfl_xor_sync(0xFFFFFFFFu, mx, o));
        }
        int wid = tid >> 5, lane = tid & 31;
        if (lane == 0){ smn[wid] = mn; smx[wid] = mx; }
    }

    // register pipeline: 3 rotating row sets
    float2 rx[3][4], ry[3][4];
    LOADROW(0, base);
    LOADROW(1, base + 1);
    #pragma unroll
    for (int r = 2; r < 8; ++r){
        int rr = base + r;
        if (rr < IMG_W){ pref2(xi + (size_t)rr * IMG_W + c0); pref2(yi + (size_t)rr * IMG_W + c0); }
    }

    __syncthreads();
    if (tid == 0){
        float mn = smn[0], mx = smx[0];
        #pragma unroll
        for (int w = 1; w < 8; ++w){ mn = fminf(mn, smn[w]); mx = fmaxf(mx, smx[w]); }
        float Ldyn = (mx > 128.0f ? 255.0f : 1.0f) - (mn < -0.5f ? -1.0f : 0.0f);
        sC[0] = (0.01f * Ldyn) * (0.01f * Ldyn);
        sC[1] = (0.03f * Ldyn) * (0.03f * Ldyn);
    }
    __syncthreads();

    const float C1 = sC[0], C2 = sC[1];
    const ull W0  = pk2(GW0, GW0), W1 = pk2(GW1, GW1);
    const ull W2  = pk2(GW2, GW2), W3 = pk2(GW3, GW3);
    const ull C1p = pk2(C1, C1),   C2p = pk2(C2, C2);
    const ull TWO = pk2(2.0f, 2.0f), NTWO = pk2(-2.0f, -2.0f), NONE = pk2(-1.0f, -1.0f);

    ull ring[6][4];
    float acc = 0.0f;

    #pragma unroll 1
    for (int i6 = 0; i6 < NROWS; i6 += 6){
        ROW_STEP(0, i6);
        ROW_STEP(1, i6);
        ROW_STEP(2, i6);
        ROW_STEP(3, i6);
        ROW_STEP(4, i6);
        ROW_STEP(5, i6);
    }

    // ---- block reduction -> partial; last block finishes ----
    #pragma unroll
    for (int o = 16; o > 0; o >>= 1)
        acc += __shfl_xor_sync(0xFFFFFFFFu, acc, o);
    const int wid = tid >> 5, lane = tid & 31;
    if (lane == 0) smn[wid] = acc;
    __syncthreads();
    if (tid == 0){
        float s = smn[0];
        #pragma unroll
        for (int w = 1; w < 8; ++w) s += smn[w];
        g_part[bx] = s;
        __threadfence();
        s_tick = atomicAdd(&g_done, 1u);
    }
    __syncthreads();

    if (s_tick == (unsigned)(nblk - 1)){
        double s = 0.0;
        for (int i = tid; i < nblk; i += 256) s += (double)g_part[i];
        #pragma unroll
        for (int o = 16; o > 0; o >>= 1)
            s += __shfl_xor_sync(0xFFFFFFFFu, s, o);
        if (lane == 0) sd[wid] = s;
        __syncthreads();
        if (tid == 0){
            double t = 0.0;
            #pragma unroll
            for (int w = 0; w < 8; ++w) t += sd[w];
            out[0] = (float)((1.0 - t * inv_n) * 0.5);
            g_done = 0u;   // reset for next graph replay
        }
    }
}

// ---------------- launch --------------------------------------------------------
extern "C" void kernel_launch(void* const* d_in, const int* in_sizes, int n_in,
                              void* d_out, int out_size){
    const float* X = (const float*)d_in[0];  // y_pred
    const float* Y = (const float*)d_in[1];  // y_true

    const int nelem = in_sizes[0];
    const int nimg  = nelem / (IMG_W * IMG_W);
    const int nblk  = NSTR * nimg;
    const double n_out = (double)nimg * (double)OUT_W * (double)OUT_W;

    k_minmax<<<NB_MM, 256>>>((const float4*)X, nelem / 4);
    k_ssim<<<nblk, 256>>>(X, Y, (float*)d_out, nblk, 1.0 / n_out);
}